// round 14
// baseline (speedup 1.0000x reference)
#include <cuda_runtime.h>
#include <cuda_fp16.h>
#include <math.h>

#define N_USERS 50000
#define N_ITEMS 100000
#define NN      150000
#define DD      64
#define NI      128
#define TS      32
#define TEMP    0.2f
#define KL_REG  0.01f
#define EMB_REG 1e-5f
#define INT_REG 1e-5f
#define SSL_REG 0.1f
#define BB      4096
#define E_TOT   3150000

#define SCAN_CHUNK 1024
#define NBLK_SCAN  ((NN + SCAN_CHUNK - 1) / SCAN_CHUNK)   // 147

#define XS 72        // padded smem row stride (halves) for mma tiles
#define SPB 8        // samples per block in k_sample

// ---------------- scratch (device globals; no allocation allowed) ------------
__device__ int   g_deg[NN];
__device__ float g_dinv[NN];
__device__ int   g_rowptr[NN + 1];
__device__ int   g_cursor[NN];
__device__ int   g_blocksum[NBLK_SCAN];
__device__ int   g_blockoff[NBLK_SCAN];
__device__ __align__(16) int2 g_csr[E_TOT];   // .x = target, .y = weight bits
__device__ __align__(16) unsigned g_curb[(size_t)NN * (DD / 2)];  // bf16x2 packed
__device__ __align__(16) unsigned g_nxtb[(size_t)NN * (DD / 2)];  // bf16x2 packed
__device__ __align__(16) float g_acc[(size_t)NN * DD];
__device__ __align__(16) __half g_ugenh[BB * DD];
__device__ __align__(16) __half g_uinth[BB * DD];
__device__ __align__(16) __half g_igenh[BB * DD];
__device__ __align__(16) __half g_iinth[BB * DD];
__device__ float g_neg[2 * BB];
__device__ float g_pos[2 * BB];
__device__ float g_sums[8];   // 0:bpr 1:kl 2:emb 3:int 4:cl

// ---------------- helpers ----------------------------------------------------
__device__ __forceinline__ float softplusf(float x) {
    return x > 0.f ? x + log1pf(expf(-x)) : log1pf(expf(x));
}

__device__ __forceinline__ float2 bf2f(unsigned x) {
    float2 r;
    r.x = __uint_as_float(x << 16);
    r.y = __uint_as_float(x & 0xffff0000u);
    return r;
}

__device__ __forceinline__ unsigned f2bf(float lo, float hi) {
    unsigned r;
    asm("cvt.rn.bf16x2.f32 %0, %1, %2;" : "=r"(r) : "f"(hi), "f"(lo));
    return r;
}

__device__ __forceinline__ float blkSum256(float v) {
    __shared__ float sp[8];
    int lane = threadIdx.x & 31, wid = threadIdx.x >> 5;
#pragma unroll
    for (int o = 16; o; o >>= 1) v += __shfl_down_sync(0xffffffffu, v, o);
    if (lane == 0) sp[wid] = v;
    __syncthreads();
    v = (threadIdx.x < 8) ? sp[threadIdx.x] : 0.f;
    if (wid == 0) {
#pragma unroll
        for (int o = 4; o; o >>= 1) v += __shfl_down_sync(0xffffffffu, v, o);
    }
    __syncthreads();
    return v;
}

__device__ __forceinline__ int blkSum256i(int v) {
    __shared__ int sp[8];
    int lane = threadIdx.x & 31, wid = threadIdx.x >> 5;
#pragma unroll
    for (int o = 16; o; o >>= 1) v += __shfl_down_sync(0xffffffffu, v, o);
    if (lane == 0) sp[wid] = v;
    __syncthreads();
    v = (threadIdx.x < 8) ? sp[threadIdx.x] : 0;
    if (wid == 0) {
#pragma unroll
        for (int o = 4; o; o >>= 1) v += __shfl_down_sync(0xffffffffu, v, o);
    }
    __syncthreads();
    return v;
}

__device__ __forceinline__ float blkSum128(float v, float* partial) {
    int lane = threadIdx.x & 31, wid = threadIdx.x >> 5;
#pragma unroll
    for (int o = 16; o; o >>= 1) v += __shfl_down_sync(0xffffffffu, v, o);
    if (lane == 0) partial[wid] = v;
    __syncthreads();
    float s = partial[0] + partial[1] + partial[2] + partial[3];
    __syncthreads();
    return s;
}

__device__ __forceinline__ float blkMax128(float v, float* partial) {
    int lane = threadIdx.x & 31, wid = threadIdx.x >> 5;
#pragma unroll
    for (int o = 16; o; o >>= 1) v = fmaxf(v, __shfl_down_sync(0xffffffffu, v, o));
    if (lane == 0) partial[wid] = v;
    __syncthreads();
    float s = fmaxf(fmaxf(partial[0], partial[1]), fmaxf(partial[2], partial[3]));
    __syncthreads();
    return s;
}

// ---------------- kernels ----------------------------------------------------
__global__ void k_clear() {
    int i = blockIdx.x * blockDim.x + threadIdx.x;
    if (i < NN) g_deg[i] = 0;
    if (i < 8) g_sums[i] = 0.f;
    if (i < 2 * BB) { g_neg[i] = 0.f; g_pos[i] = 0.f; }
}

__global__ void k_deg(const int* __restrict__ hl, int E) {
    int e = blockIdx.x * blockDim.x + threadIdx.x;
    if (e < E) atomicAdd(&g_deg[hl[e]], 1);
}

__global__ void k_scanA() {
    int base = blockIdx.x * SCAN_CHUNK;
    int v = 0;
    for (int i = threadIdx.x; i < SCAN_CHUNK; i += 256) {
        int idx = base + i;
        if (idx < NN) {
            int d = g_deg[idx];
            v += d;
            g_dinv[idx] = rsqrtf((float)d);
        }
    }
    int tot = blkSum256i(v);
    if (threadIdx.x == 0) g_blocksum[blockIdx.x] = tot;
}

__global__ void k_scanB() {
    int lane = threadIdx.x;
    int v[5]; int s = 0;
#pragma unroll
    for (int j = 0; j < 5; j++) {
        int i = lane * 5 + j;
        v[j] = (i < NBLK_SCAN) ? g_blocksum[i] : 0;
        s += v[j];
    }
    int t = s;
#pragma unroll
    for (int o = 1; o < 32; o <<= 1) {
        int x = __shfl_up_sync(0xffffffffu, t, o);
        if (lane >= o) t += x;
    }
    int run = t - s;
#pragma unroll
    for (int j = 0; j < 5; j++) {
        int i = lane * 5 + j;
        if (i < NBLK_SCAN) g_blockoff[i] = run;
        run += v[j];
    }
    if (lane == 31) g_rowptr[NN] = t;
}

__global__ void k_scanC() {
    __shared__ int wsum[8];
    int base = blockIdx.x * SCAN_CHUNK;
    int tid = threadIdx.x, lane = tid & 31, wid = tid >> 5;
    int v[4]; int s = 0;
#pragma unroll
    for (int j = 0; j < 4; j++) {
        int i = base + tid * 4 + j;
        v[j] = (i < NN) ? g_deg[i] : 0;
        s += v[j];
    }
    int t = s;
#pragma unroll
    for (int o = 1; o < 32; o <<= 1) {
        int x = __shfl_up_sync(0xffffffffu, t, o);
        if (lane >= o) t += x;
    }
    if (lane == 31) wsum[wid] = t;
    __syncthreads();
    if (wid == 0 && lane < 8) {
        int w = wsum[lane];
#pragma unroll
        for (int o = 1; o < 8; o <<= 1) {
            int x = __shfl_up_sync(0xffu, w, o);
            if (lane >= o) w += x;
        }
        wsum[lane] = w;
    }
    __syncthreads();
    int run = g_blockoff[blockIdx.x] + ((wid > 0) ? wsum[wid - 1] : 0) + (t - s);
#pragma unroll
    for (int j = 0; j < 4; j++) {
        int i = base + tid * 4 + j;
        if (i < NN) { g_rowptr[i] = run; g_cursor[i] = run; }
        run += v[j];
    }
}

__global__ void k_scatter(const int* __restrict__ hl, const int* __restrict__ tl, int E) {
    int e = blockIdx.x * blockDim.x + threadIdx.x;
    if (e >= E) return;
    int h = hl[e], t = tl[e];
    int idx = atomicAdd(&g_cursor[h], 1);
    g_csr[idx] = make_int2(t, __float_as_int(g_dinv[h] * g_dinv[t]));
}

__global__ void k_init(const float* __restrict__ ue, const float* __restrict__ ie) {
    int i = blockIdx.x * blockDim.x + threadIdx.x;
    if (i >= NN * (DD / 2)) return;
    int n = i >> 5, h = i & 31;
    const float* src = (n < N_USERS) ? (ue + (size_t)n * DD) : (ie + (size_t)(n - N_USERS) * DD);
    float2 v = make_float2(src[h * 2], src[h * 2 + 1]);
    g_curb[i] = f2bf(v.x, v.y);
    ((float2*)g_acc)[i] = v;
}

// one warp per node; lane handles 2 dims (one bf16x2); int2 CSR; 4-edge unroll.
__global__ void k_prop(const unsigned* __restrict__ src, unsigned* __restrict__ dst) {
    int gw = (blockIdx.x * blockDim.x + threadIdx.x) >> 5;
    int lane = threadIdx.x & 31;
    if (gw >= NN) return;
    int s = g_rowptr[gw], e = g_rowptr[gw + 1];
    float a0 = 0.f, a1 = 0.f;
    int k = s;
    for (; k + 3 < e; k += 4) {
        int2 e0 = __ldg(&g_csr[k]),     e1 = __ldg(&g_csr[k + 1]);
        int2 e2 = __ldg(&g_csr[k + 2]), e3 = __ldg(&g_csr[k + 3]);
        unsigned b0 = __ldg(&src[(size_t)e0.x * 32 + lane]);
        unsigned b1 = __ldg(&src[(size_t)e1.x * 32 + lane]);
        unsigned b2 = __ldg(&src[(size_t)e2.x * 32 + lane]);
        unsigned b3 = __ldg(&src[(size_t)e3.x * 32 + lane]);
        float2 v0 = bf2f(b0), v1 = bf2f(b1), v2 = bf2f(b2), v3 = bf2f(b3);
        float w0 = __int_as_float(e0.y), w1 = __int_as_float(e1.y);
        float w2 = __int_as_float(e2.y), w3 = __int_as_float(e3.y);
        a0 += w0 * v0.x + w1 * v1.x + w2 * v2.x + w3 * v3.x;
        a1 += w0 * v0.y + w1 * v1.y + w2 * v2.y + w3 * v3.y;
    }
    for (; k < e; k++) {
        int2 ed = __ldg(&g_csr[k]);
        float2 v = bf2f(__ldg(&src[(size_t)ed.x * 32 + lane]));
        float w = __int_as_float(ed.y);
        a0 += w * v.x;
        a1 += w * v.y;
    }
    dst[(size_t)gw * 32 + lane] = f2bf(a0, a1);
    float2* ap = (float2*)g_acc + (size_t)gw * 32 + lane;
    float2 av = *ap;
    av.x += a0; av.y += a1;
    *ap = av;
}

// KL term over all N rows. block = 256 = 4 rows x 64 dims.
__global__ void k_kl(const float* __restrict__ lw, const float* __restrict__ lb) {
    __shared__ float swT[TS * DD];
    __shared__ float sb[DD];
    __shared__ float ss[4][TS];
    int tid = threadIdx.x;
    for (int i = tid; i < TS * DD; i += 256) {
        int d = i >> 5, t = i & 31;
        swT[t * DD + d] = lw[i];
    }
    if (tid < DD) sb[tid] = lb[tid];
    __syncthreads();
    int r = tid >> 6;
    int d = tid & 63;
    int row = blockIdx.x * 4 + r;
    if (row < NN && d < TS) ss[r][d] = softplusf(g_acc[(size_t)row * DD + d]);
    __syncthreads();
    float klv = 0.f;
    if (row < NN) {
        float stdv = sb[d] + 1e-8f;
#pragma unroll
        for (int t = 0; t < TS; t++) stdv += ss[r][t] * swT[t * DD + d];
        float mn = g_acc[(size_t)row * DD + d];
        float kl = -0.5f * (1.f + 2.f * stdv - mn * mn - expf(2.f * stdv));
        if (isfinite(kl)) klv = kl;
    }
    float tot = blkSum256(klv);
    if (tid == 0) atomicAdd(&g_sums[1], tot);
}

// BPR + embedding-reg over B samples; one warp per sample.
__global__ void k_bpr(const float* __restrict__ ue, const float* __restrict__ ie,
                      const int* __restrict__ users, const int* __restrict__ pos,
                      const int* __restrict__ neg) {
    int w = (blockIdx.x * blockDim.x + threadIdx.x) >> 5;
    int lane = threadIdx.x & 31;
    if (w >= BB) return;
    int u = users[w], p = pos[w], n = neg[w];
    const float* au = g_acc + (size_t)u * DD;
    const float* ap = g_acc + (size_t)(N_USERS + p) * DD;
    const float* an = g_acc + (size_t)(N_USERS + n) * DD;
    float ps = 0.f, ns = 0.f, es = 0.f;
#pragma unroll
    for (int j = 0; j < 2; j++) {
        int d = lane + 32 * j;
        float x = au[d];
        ps += x * ap[d];
        ns += x * an[d];
        float a = ue[(size_t)u * DD + d], b = ie[(size_t)p * DD + d], c = ie[(size_t)n * DD + d];
        es += a * a + b * b + c * c;
    }
#pragma unroll
    for (int o = 16; o; o >>= 1) {
        ps += __shfl_down_sync(0xffffffffu, ps, o);
        ns += __shfl_down_sync(0xffffffffu, ns, o);
        es += __shfl_down_sync(0xffffffffu, es, o);
    }
    if (lane == 0) {
        atomicAdd(&g_sums[0], softplusf(ns - ps));
        atomicAdd(&g_sums[2], es);
    }
}

// intent regularizer
__global__ void k_intreg(const float* __restrict__ ui, const float* __restrict__ ii) {
    int i = blockIdx.x * blockDim.x + threadIdx.x;
    float v = 0.f;
    if (i < DD * NI)            { float a = ui[i];           v = a * a; }
    else if (i < 2 * DD * NI)   { float a = ii[i - DD * NI]; v = a * a; }
    float tot = blkSum256(v);
    if (threadIdx.x == 0) atomicAdd(&g_sums[3], tot);
}

// per-sample features, batched: SPB samples per block, intent matrix cached in
// padded smem (conflict-free row+column reads). grid = 2*BB/SPB, block = 128.
__global__ void k_sample(const float* __restrict__ lw, const float* __restrict__ lb,
                         const float* __restrict__ eps,
                         const float* __restrict__ uintm, const float* __restrict__ iintm,
                         const int* __restrict__ users, const int* __restrict__ pos) {
    __shared__ float sint[DD][NI + 1];   // 33KB, padded
    __shared__ float slw[DD * TS];
    __shared__ float slb[DD];
    __shared__ float mrow[DD];
    __shared__ float sp[TS];
    __shared__ float prob[NI];
    __shared__ float partial[4];
    int tid = threadIdx.x;
    int side = blockIdx.x >> 9;                 // 2*BB/SPB = 1024 blocks; 512/side
    int b0 = (blockIdx.x & 511) * SPB;
    const float* intent = side ? iintm : uintm;
    __half* outgen = side ? g_igenh : g_ugenh;
    __half* outint = side ? g_iinth : g_uinth;

    for (int i = tid; i < DD * NI; i += 128) sint[i >> 7][i & 127] = intent[i];
    for (int i = tid; i < DD * TS; i += 128) slw[i] = lw[i];
    if (tid < DD) slb[tid] = lb[tid];
    __syncthreads();

    for (int s = 0; s < SPB; s++) {
        int b = b0 + s;
        int node = side ? (N_USERS + pos[b]) : users[b];

        if (tid < DD) mrow[tid] = g_acc[(size_t)node * DD + tid];
        __syncthreads();
        if (tid < TS) sp[tid] = softplusf(mrow[tid]);
        __syncthreads();

        float genv = 0.f;
        if (tid < DD) {
            float stdv = slb[tid] + 1e-8f;
#pragma unroll
            for (int t = 0; t < TS; t++) stdv += sp[t] * slw[tid * TS + t];
            genv = mrow[tid] + eps[(size_t)node * DD + tid] * stdv;
        }
        float gn2 = blkSum128(genv * genv, partial);
        float genn = genv * rsqrtf(gn2);
        if (tid < DD) outgen[b * DD + tid] = __float2half(genn);

        float lg = 0.f;
#pragma unroll
        for (int d = 0; d < DD; d++) lg += mrow[d] * sint[d][tid];
        float mx = blkMax128(lg, partial);
        float ev = expf(lg - mx);
        float ssum = blkSum128(ev, partial);
        prob[tid] = ev;
        __syncthreads();

        float o = 0.f;
        if (tid < DD) {
#pragma unroll
            for (int k = 0; k < NI; k++) o += sint[tid][k] * prob[k];
            o /= ssum;
        }
        float on2 = blkSum128(o * o, partial);
        float on = o * rsqrtf(on2);
        if (tid < DD) outint[b * DD + tid] = __float2half(on);

        float dot = blkSum128((tid < DD) ? genn * on : 0.f, partial);
        if (tid == 0) g_pos[side * BB + b] = __expf(dot * (1.f / TEMP));
        __syncthreads();
    }
}

// InfoNCE negative sums via HMMA. grid (BB/128, BB/64, 2), block 256 (8 warps).
__global__ void k_nce_mma() {
    __shared__ __align__(16) __half As[128 * XS];
    __shared__ __align__(16) __half Bs[64 * XS];
    int z = blockIdx.z;
    const __half* e1 = z ? g_igenh : g_ugenh;
    const __half* e2 = z ? g_iinth : g_uinth;
    float* negbuf = g_neg + z * BB;
    int tid = threadIdx.x;
    int w = tid >> 5, lane = tid & 31;
    int i0 = blockIdx.x * 128, j0 = blockIdx.y * 64;

    {
        const uint4* ga = (const uint4*)(e1 + (size_t)i0 * DD);
#pragma unroll
        for (int q = 0; q < 4; q++) {
            int c = tid + q * 256;
            int row = c >> 3, ch = c & 7;
            *(uint4*)&As[row * XS + ch * 8] = ga[row * 8 + ch];
        }
        const uint4* gb = (const uint4*)(e2 + (size_t)j0 * DD);
#pragma unroll
        for (int q = 0; q < 2; q++) {
            int c = tid + q * 256;
            int row = c >> 3, ch = c & 7;
            *(uint4*)&Bs[row * XS + ch * 8] = gb[row * 8 + ch];
        }
    }
    __syncthreads();

    unsigned a[4][4];
#pragma unroll
    for (int ks = 0; ks < 4; ks++) {
        int r = w * 16 + (lane & 15);
        int c = ks * 16 + (lane >> 4) * 8;
        unsigned addr = (unsigned)__cvta_generic_to_shared(&As[r * XS + c]);
        asm volatile("ldmatrix.sync.aligned.m8n8.x4.shared.b16 {%0,%1,%2,%3}, [%4];"
                     : "=r"(a[ks][0]), "=r"(a[ks][1]), "=r"(a[ks][2]), "=r"(a[ks][3])
                     : "r"(addr));
    }

    const float invT = 1.f / TEMP;
    float negs_lo = 0.f, negs_hi = 0.f;
#pragma unroll
    for (int nt = 0; nt < 8; nt++) {
        float c0 = 0.f, c1 = 0.f, c2 = 0.f, c3 = 0.f;
#pragma unroll
        for (int ks = 0; ks < 4; ks++) {
            int br = nt * 8 + (lane & 7);
            int bc = ks * 16 + ((lane >> 3) & 1) * 8;
            unsigned baddr = (unsigned)__cvta_generic_to_shared(&Bs[br * XS + bc]);
            unsigned b0, b1;
            asm volatile("ldmatrix.sync.aligned.m8n8.x2.shared.b16 {%0,%1}, [%2];"
                         : "=r"(b0), "=r"(b1) : "r"(baddr));
            asm volatile("mma.sync.aligned.m16n8k16.row.col.f32.f16.f16.f32 "
                         "{%0,%1,%2,%3}, {%4,%5,%6,%7}, {%8,%9}, {%0,%1,%2,%3};"
                         : "+f"(c0), "+f"(c1), "+f"(c2), "+f"(c3)
                         : "r"(a[ks][0]), "r"(a[ks][1]), "r"(a[ks][2]), "r"(a[ks][3]),
                           "r"(b0), "r"(b1));
        }
        float sl = __expf(c0 * invT) + __expf(c1 * invT);
        float sh = __expf(c2 * invT) + __expf(c3 * invT);
        sl += __shfl_xor_sync(0xffffffffu, sl, 1);
        sl += __shfl_xor_sync(0xffffffffu, sl, 2);
        sh += __shfl_xor_sync(0xffffffffu, sh, 1);
        sh += __shfl_xor_sync(0xffffffffu, sh, 2);
        negs_lo += sl;
        negs_hi += sh;
    }
    if ((lane & 3) == 0) {
        int r = lane >> 2;
        atomicAdd(&negbuf[i0 + w * 16 + r], negs_lo);
        atomicAdd(&negbuf[i0 + w * 16 + r + 8], negs_hi);
    }
}

// fused nce-final + output (single block of 256)
__global__ void k_final(float* __restrict__ out) {
    int tid = threadIdx.x;
    float cl = 0.f;
    for (int i = tid; i < 2 * BB; i += 256)
        cl += -logf(g_pos[i] / (g_neg[i] + 1e-8f) + 1e-8f);
    float cltot = blkSum256(cl);
    if (tid == 0) {
        float bpr = g_sums[0] / (float)BB;
        float kl  = KL_REG * (g_sums[1] / (float)NN);
        out[0] = bpr + kl;
        out[1] = SSL_REG * (cltot / (float)BB);
        out[2] = EMB_REG * g_sums[2];
        out[3] = INT_REG * g_sums[3];
    }
}

// ---------------- launch ------------------------------------------------------
extern "C" void kernel_launch(void* const* d_in, const int* in_sizes, int n_in,
                              void* d_out, int out_size) {
    const float* user_emb = (const float*)d_in[0];
    const float* item_emb = (const float*)d_in[1];
    const float* uintm    = (const float*)d_in[2];
    const float* iintm    = (const float*)d_in[3];
    const float* lw       = (const float*)d_in[4];
    const float* lb       = (const float*)d_in[5];
    const float* eps      = (const float*)d_in[6];
    const int*   hl       = (const int*)d_in[7];
    const int*   tl       = (const int*)d_in[8];
    const int*   users    = (const int*)d_in[9];
    const int*   pos      = (const int*)d_in[10];
    const int*   neg      = (const int*)d_in[11];
    int E = in_sizes[7];
    float* out = (float*)d_out;

    void *p_cur, *p_nxt;
    cudaGetSymbolAddress(&p_cur, g_curb);
    cudaGetSymbolAddress(&p_nxt, g_nxtb);

    k_clear<<<(NN + 255) / 256, 256>>>();
    k_deg<<<(E + 255) / 256, 256>>>(hl, E);
    k_scanA<<<NBLK_SCAN, 256>>>();
    k_scanB<<<1, 32>>>();
    k_scanC<<<NBLK_SCAN, 256>>>();
    k_scatter<<<(E + 255) / 256, 256>>>(hl, tl, E);
    k_init<<<(NN * (DD / 2) + 255) / 256, 256>>>(user_emb, item_emb);

    k_prop<<<(NN * 32 + 255) / 256, 256>>>((const unsigned*)p_cur, (unsigned*)p_nxt);
    k_prop<<<(NN * 32 + 255) / 256, 256>>>((const unsigned*)p_nxt, (unsigned*)p_cur);
    k_prop<<<(NN * 32 + 255) / 256, 256>>>((const unsigned*)p_cur, (unsigned*)p_nxt);

    k_kl<<<(NN + 3) / 4, 256>>>(lw, lb);
    k_bpr<<<(BB * 32 + 255) / 256, 256>>>(user_emb, item_emb, users, pos, neg);
    k_intreg<<<(2 * DD * NI + 255) / 256, 256>>>(uintm, iintm);
    k_sample<<<2 * BB / SPB, 128>>>(lw, lb, eps, uintm, iintm, users, pos);

    {
        dim3 grid(BB / 128, BB / 64, 2);
        k_nce_mma<<<grid, 256>>>();
    }
    k_final<<<1, 256>>>(out);
}

// round 17
// speedup vs baseline: 1.5894x; 1.5894x over previous
#include <cuda_runtime.h>
#include <cuda_fp16.h>
#include <math.h>

#define N_USERS 50000
#define N_ITEMS 100000
#define NN      150000
#define DD      64
#define NI      128
#define TS      32
#define TEMP    0.2f
#define KL_REG  0.01f
#define EMB_REG 1e-5f
#define INT_REG 1e-5f
#define SSL_REG 0.1f
#define BB      4096
#define E_TOT   3150000

#define SCAN_CHUNK 1024
#define NBLK_SCAN  ((NN + SCAN_CHUNK - 1) / SCAN_CHUNK)   // 147

#define XS 72        // padded smem row stride (halves) for mma tiles
#define SPB 4        // samples per block in k_sample

// ---------------- scratch (device globals; no allocation allowed) ------------
__device__ int   g_deg[NN];
__device__ float g_dinv[NN];
__device__ int   g_rowptr[NN + 1];
__device__ int   g_cursor[NN];
__device__ int   g_blocksum[NBLK_SCAN];
__device__ int   g_blockoff[NBLK_SCAN];
__device__ int   g_csr_t[E_TOT];
__device__ float g_csr_g[E_TOT];
__device__ __align__(16) unsigned g_curb[(size_t)NN * (DD / 2)];  // bf16x2 packed
__device__ __align__(16) unsigned g_nxtb[(size_t)NN * (DD / 2)];  // bf16x2 packed
__device__ __align__(16) float g_acc[(size_t)NN * DD];
__device__ __align__(16) __half g_ugenh[BB * DD];
__device__ __align__(16) __half g_uinth[BB * DD];
__device__ __align__(16) __half g_igenh[BB * DD];
__device__ __align__(16) __half g_iinth[BB * DD];
__device__ float g_neg[2 * BB];
__device__ float g_pos[2 * BB];
__device__ float g_sums[8];   // 0:bpr 1:kl 2:emb 3:int 4:cl

// ---------------- helpers ----------------------------------------------------
__device__ __forceinline__ float softplusf(float x) {
    return x > 0.f ? x + log1pf(expf(-x)) : log1pf(expf(x));
}

__device__ __forceinline__ float2 bf2f(unsigned x) {
    float2 r;
    r.x = __uint_as_float(x << 16);
    r.y = __uint_as_float(x & 0xffff0000u);
    return r;
}

__device__ __forceinline__ unsigned f2bf(float lo, float hi) {
    unsigned r;
    asm("cvt.rn.bf16x2.f32 %0, %1, %2;" : "=r"(r) : "f"(hi), "f"(lo));
    return r;
}

__device__ __forceinline__ float blkSum256(float v) {
    __shared__ float sp[8];
    int lane = threadIdx.x & 31, wid = threadIdx.x >> 5;
#pragma unroll
    for (int o = 16; o; o >>= 1) v += __shfl_down_sync(0xffffffffu, v, o);
    if (lane == 0) sp[wid] = v;
    __syncthreads();
    v = (threadIdx.x < 8) ? sp[threadIdx.x] : 0.f;
    if (wid == 0) {
#pragma unroll
        for (int o = 4; o; o >>= 1) v += __shfl_down_sync(0xffffffffu, v, o);
    }
    __syncthreads();
    return v;
}

__device__ __forceinline__ int blkSum256i(int v) {
    __shared__ int sp[8];
    int lane = threadIdx.x & 31, wid = threadIdx.x >> 5;
#pragma unroll
    for (int o = 16; o; o >>= 1) v += __shfl_down_sync(0xffffffffu, v, o);
    if (lane == 0) sp[wid] = v;
    __syncthreads();
    v = (threadIdx.x < 8) ? sp[threadIdx.x] : 0;
    if (wid == 0) {
#pragma unroll
        for (int o = 4; o; o >>= 1) v += __shfl_down_sync(0xffffffffu, v, o);
    }
    __syncthreads();
    return v;
}

__device__ __forceinline__ float blkSum128(float v, float* partial) {
    int lane = threadIdx.x & 31, wid = threadIdx.x >> 5;
#pragma unroll
    for (int o = 16; o; o >>= 1) v += __shfl_down_sync(0xffffffffu, v, o);
    if (lane == 0) partial[wid] = v;
    __syncthreads();
    float s = partial[0] + partial[1] + partial[2] + partial[3];
    __syncthreads();
    return s;
}

__device__ __forceinline__ float blkMax128(float v, float* partial) {
    int lane = threadIdx.x & 31, wid = threadIdx.x >> 5;
#pragma unroll
    for (int o = 16; o; o >>= 1) v = fmaxf(v, __shfl_down_sync(0xffffffffu, v, o));
    if (lane == 0) partial[wid] = v;
    __syncthreads();
    float s = fmaxf(fmaxf(partial[0], partial[1]), fmaxf(partial[2], partial[3]));
    __syncthreads();
    return s;
}

// ---------------- kernels ----------------------------------------------------
__global__ void k_clear() {
    int i = blockIdx.x * blockDim.x + threadIdx.x;
    if (i < NN) g_deg[i] = 0;
    if (i < 8) g_sums[i] = 0.f;
    if (i < 2 * BB) { g_neg[i] = 0.f; g_pos[i] = 0.f; }
}

__global__ void k_deg(const int* __restrict__ hl, int E) {
    int e = blockIdx.x * blockDim.x + threadIdx.x;
    if (e < E) atomicAdd(&g_deg[hl[e]], 1);
}

__global__ void k_scanA() {
    int base = blockIdx.x * SCAN_CHUNK;
    int v = 0;
    for (int i = threadIdx.x; i < SCAN_CHUNK; i += 256) {
        int idx = base + i;
        if (idx < NN) {
            int d = g_deg[idx];
            v += d;
            g_dinv[idx] = rsqrtf((float)d);
        }
    }
    int tot = blkSum256i(v);
    if (threadIdx.x == 0) g_blocksum[blockIdx.x] = tot;
}

__global__ void k_scanB() {
    int lane = threadIdx.x;
    int v[5]; int s = 0;
#pragma unroll
    for (int j = 0; j < 5; j++) {
        int i = lane * 5 + j;
        v[j] = (i < NBLK_SCAN) ? g_blocksum[i] : 0;
        s += v[j];
    }
    int t = s;
#pragma unroll
    for (int o = 1; o < 32; o <<= 1) {
        int x = __shfl_up_sync(0xffffffffu, t, o);
        if (lane >= o) t += x;
    }
    int run = t - s;
#pragma unroll
    for (int j = 0; j < 5; j++) {
        int i = lane * 5 + j;
        if (i < NBLK_SCAN) g_blockoff[i] = run;
        run += v[j];
    }
    if (lane == 31) g_rowptr[NN] = t;
}

__global__ void k_scanC() {
    __shared__ int wsum[8];
    int base = blockIdx.x * SCAN_CHUNK;
    int tid = threadIdx.x, lane = tid & 31, wid = tid >> 5;
    int v[4]; int s = 0;
#pragma unroll
    for (int j = 0; j < 4; j++) {
        int i = base + tid * 4 + j;
        v[j] = (i < NN) ? g_deg[i] : 0;
        s += v[j];
    }
    int t = s;
#pragma unroll
    for (int o = 1; o < 32; o <<= 1) {
        int x = __shfl_up_sync(0xffffffffu, t, o);
        if (lane >= o) t += x;
    }
    if (lane == 31) wsum[wid] = t;
    __syncthreads();
    if (wid == 0 && lane < 8) {
        int w = wsum[lane];
#pragma unroll
        for (int o = 1; o < 8; o <<= 1) {
            int x = __shfl_up_sync(0xffu, w, o);
            if (lane >= o) w += x;
        }
        wsum[lane] = w;
    }
    __syncthreads();
    int run = g_blockoff[blockIdx.x] + ((wid > 0) ? wsum[wid - 1] : 0) + (t - s);
#pragma unroll
    for (int j = 0; j < 4; j++) {
        int i = base + tid * 4 + j;
        if (i < NN) { g_rowptr[i] = run; g_cursor[i] = run; }
        run += v[j];
    }
}

__global__ void k_scatter(const int* __restrict__ hl, const int* __restrict__ tl, int E) {
    int e = blockIdx.x * blockDim.x + threadIdx.x;
    if (e >= E) return;
    int h = hl[e], t = tl[e];
    int idx = atomicAdd(&g_cursor[h], 1);
    g_csr_t[idx] = t;
    g_csr_g[idx] = g_dinv[h] * g_dinv[t];
}

__global__ void k_init(const float* __restrict__ ue, const float* __restrict__ ie) {
    int i = blockIdx.x * blockDim.x + threadIdx.x;
    if (i >= NN * (DD / 2)) return;
    int n = i >> 5, h = i & 31;
    const float* src = (n < N_USERS) ? (ue + (size_t)n * DD) : (ie + (size_t)(n - N_USERS) * DD);
    float2 v = make_float2(src[h * 2], src[h * 2 + 1]);
    g_curb[i] = f2bf(v.x, v.y);
    ((float2*)g_acc)[i] = v;
}

// one warp per node; lane handles 2 dims (one bf16x2); 4-edge unroll (R13-proven).
__global__ void k_prop(const unsigned* __restrict__ src, unsigned* __restrict__ dst) {
    int gw = (blockIdx.x * blockDim.x + threadIdx.x) >> 5;
    int lane = threadIdx.x & 31;
    if (gw >= NN) return;
    int s = g_rowptr[gw], e = g_rowptr[gw + 1];
    float a0 = 0.f, a1 = 0.f;
    int k = s;
    for (; k + 3 < e; k += 4) {
        int   t0 = __ldg(&g_csr_t[k]),     t1 = __ldg(&g_csr_t[k + 1]);
        int   t2 = __ldg(&g_csr_t[k + 2]), t3 = __ldg(&g_csr_t[k + 3]);
        float w0 = __ldg(&g_csr_g[k]),     w1 = __ldg(&g_csr_g[k + 1]);
        float w2 = __ldg(&g_csr_g[k + 2]), w3 = __ldg(&g_csr_g[k + 3]);
        unsigned b0 = __ldg(&src[(size_t)t0 * 32 + lane]);
        unsigned b1 = __ldg(&src[(size_t)t1 * 32 + lane]);
        unsigned b2 = __ldg(&src[(size_t)t2 * 32 + lane]);
        unsigned b3 = __ldg(&src[(size_t)t3 * 32 + lane]);
        float2 v0 = bf2f(b0), v1 = bf2f(b1), v2 = bf2f(b2), v3 = bf2f(b3);
        a0 += w0 * v0.x + w1 * v1.x + w2 * v2.x + w3 * v3.x;
        a1 += w0 * v0.y + w1 * v1.y + w2 * v2.y + w3 * v3.y;
    }
    for (; k < e; k++) {
        int t0 = __ldg(&g_csr_t[k]); float w0 = __ldg(&g_csr_g[k]);
        float2 v0 = bf2f(__ldg(&src[(size_t)t0 * 32 + lane]));
        a0 += w0 * v0.x;
        a1 += w0 * v0.y;
    }
    dst[(size_t)gw * 32 + lane] = f2bf(a0, a1);
    float2* ap = (float2*)g_acc + (size_t)gw * 32 + lane;
    float2 av = *ap;
    av.x += a0; av.y += a1;
    *ap = av;
}

// KL term over all N rows. block = 256 = 4 rows x 64 dims.
__global__ void k_kl(const float* __restrict__ lw, const float* __restrict__ lb) {
    __shared__ float swT[TS * DD];
    __shared__ float sb[DD];
    __shared__ float ss[4][TS];
    int tid = threadIdx.x;
    for (int i = tid; i < TS * DD; i += 256) {
        int d = i >> 5, t = i & 31;
        swT[t * DD + d] = lw[i];
    }
    if (tid < DD) sb[tid] = lb[tid];
    __syncthreads();
    int r = tid >> 6;
    int d = tid & 63;
    int row = blockIdx.x * 4 + r;
    if (row < NN && d < TS) ss[r][d] = softplusf(g_acc[(size_t)row * DD + d]);
    __syncthreads();
    float klv = 0.f;
    if (row < NN) {
        float stdv = sb[d] + 1e-8f;
#pragma unroll
        for (int t = 0; t < TS; t++) stdv += ss[r][t] * swT[t * DD + d];
        float mn = g_acc[(size_t)row * DD + d];
        float kl = -0.5f * (1.f + 2.f * stdv - mn * mn - expf(2.f * stdv));
        if (isfinite(kl)) klv = kl;
    }
    float tot = blkSum256(klv);
    if (tid == 0) atomicAdd(&g_sums[1], tot);
}

// BPR + embedding-reg over B samples; one warp per sample.
__global__ void k_bpr(const float* __restrict__ ue, const float* __restrict__ ie,
                      const int* __restrict__ users, const int* __restrict__ pos,
                      const int* __restrict__ neg) {
    int w = (blockIdx.x * blockDim.x + threadIdx.x) >> 5;
    int lane = threadIdx.x & 31;
    if (w >= BB) return;
    int u = users[w], p = pos[w], n = neg[w];
    const float* au = g_acc + (size_t)u * DD;
    const float* ap = g_acc + (size_t)(N_USERS + p) * DD;
    const float* an = g_acc + (size_t)(N_USERS + n) * DD;
    float ps = 0.f, ns = 0.f, es = 0.f;
#pragma unroll
    for (int j = 0; j < 2; j++) {
        int d = lane + 32 * j;
        float x = au[d];
        ps += x * ap[d];
        ns += x * an[d];
        float a = ue[(size_t)u * DD + d], b = ie[(size_t)p * DD + d], c = ie[(size_t)n * DD + d];
        es += a * a + b * b + c * c;
    }
#pragma unroll
    for (int o = 16; o; o >>= 1) {
        ps += __shfl_down_sync(0xffffffffu, ps, o);
        ns += __shfl_down_sync(0xffffffffu, ns, o);
        es += __shfl_down_sync(0xffffffffu, es, o);
    }
    if (lane == 0) {
        atomicAdd(&g_sums[0], softplusf(ns - ps));
        atomicAdd(&g_sums[2], es);
    }
}

// intent regularizer
__global__ void k_intreg(const float* __restrict__ ui, const float* __restrict__ ii) {
    int i = blockIdx.x * blockDim.x + threadIdx.x;
    float v = 0.f;
    if (i < DD * NI)            { float a = ui[i];           v = a * a; }
    else if (i < 2 * DD * NI)   { float a = ii[i - DD * NI]; v = a * a; }
    float tot = blkSum256(v);
    if (threadIdx.x == 0) atomicAdd(&g_sums[3], tot);
}

// per-sample features, batched: SPB samples per block, intent matrix cached in
// padded smem. grid = 2*BB/SPB = 2048, block = 128.
__global__ void k_sample(const float* __restrict__ lw, const float* __restrict__ lb,
                         const float* __restrict__ eps,
                         const float* __restrict__ uintm, const float* __restrict__ iintm,
                         const int* __restrict__ users, const int* __restrict__ pos) {
    __shared__ float sint[DD][NI + 1];   // 33KB, padded
    __shared__ float slw[DD * TS];
    __shared__ float slb[DD];
    __shared__ float mrow[DD];
    __shared__ float sp[TS];
    __shared__ float prob[NI];
    __shared__ float partial[4];
    int tid = threadIdx.x;
    int side = blockIdx.x >> 10;                // 2048 blocks; 1024 per side
    int b0 = (blockIdx.x & 1023) * SPB;
    const float* intent = side ? iintm : uintm;
    __half* outgen = side ? g_igenh : g_ugenh;
    __half* outint = side ? g_iinth : g_uinth;

    for (int i = tid; i < DD * NI; i += 128) sint[i >> 7][i & 127] = intent[i];
    for (int i = tid; i < DD * TS; i += 128) slw[i] = lw[i];
    if (tid < DD) slb[tid] = lb[tid];
    __syncthreads();

    for (int s = 0; s < SPB; s++) {
        int b = b0 + s;
        int node = side ? (N_USERS + pos[b]) : users[b];

        if (tid < DD) mrow[tid] = g_acc[(size_t)node * DD + tid];
        __syncthreads();
        if (tid < TS) sp[tid] = softplusf(mrow[tid]);
        __syncthreads();

        float genv = 0.f;
        if (tid < DD) {
            float stdv = slb[tid] + 1e-8f;
#pragma unroll
            for (int t = 0; t < TS; t++) stdv += sp[t] * slw[tid * TS + t];
            genv = mrow[tid] + eps[(size_t)node * DD + tid] * stdv;
        }
        float gn2 = blkSum128(genv * genv, partial);
        float genn = genv * rsqrtf(gn2);
        if (tid < DD) outgen[b * DD + tid] = __float2half(genn);

        float lg = 0.f;
#pragma unroll
        for (int d = 0; d < DD; d++) lg += mrow[d] * sint[d][tid];
        float mx = blkMax128(lg, partial);
        float ev = expf(lg - mx);
        float ssum = blkSum128(ev, partial);
        prob[tid] = ev;
        __syncthreads();

        float o = 0.f;
        if (tid < DD) {
#pragma unroll
            for (int k = 0; k < NI; k++) o += sint[tid][k] * prob[k];
            o /= ssum;
        }
        float on2 = blkSum128(o * o, partial);
        float on = o * rsqrtf(on2);
        if (tid < DD) outint[b * DD + tid] = __float2half(on);

        float dot = blkSum128((tid < DD) ? genn * on : 0.f, partial);
        if (tid == 0) g_pos[side * BB + b] = __expf(dot * (1.f / TEMP));
        __syncthreads();
    }
}

// InfoNCE negative sums via HMMA. grid (BB/128, BB/64, 2), block 256 (8 warps).
__global__ void k_nce_mma() {
    __shared__ __align__(16) __half As[128 * XS];
    __shared__ __align__(16) __half Bs[64 * XS];
    int z = blockIdx.z;
    const __half* e1 = z ? g_igenh : g_ugenh;
    const __half* e2 = z ? g_iinth : g_uinth;
    float* negbuf = g_neg + z * BB;
    int tid = threadIdx.x;
    int w = tid >> 5, lane = tid & 31;
    int i0 = blockIdx.x * 128, j0 = blockIdx.y * 64;

    {
        const uint4* ga = (const uint4*)(e1 + (size_t)i0 * DD);
#pragma unroll
        for (int q = 0; q < 4; q++) {
            int c = tid + q * 256;
            int row = c >> 3, ch = c & 7;
            *(uint4*)&As[row * XS + ch * 8] = ga[row * 8 + ch];
        }
        const uint4* gb = (const uint4*)(e2 + (size_t)j0 * DD);
#pragma unroll
        for (int q = 0; q < 2; q++) {
            int c = tid + q * 256;
            int row = c >> 3, ch = c & 7;
            *(uint4*)&Bs[row * XS + ch * 8] = gb[row * 8 + ch];
        }
    }
    __syncthreads();

    unsigned a[4][4];
#pragma unroll
    for (int ks = 0; ks < 4; ks++) {
        int r = w * 16 + (lane & 15);
        int c = ks * 16 + (lane >> 4) * 8;
        unsigned addr = (unsigned)__cvta_generic_to_shared(&As[r * XS + c]);
        asm volatile("ldmatrix.sync.aligned.m8n8.x4.shared.b16 {%0,%1,%2,%3}, [%4];"
                     : "=r"(a[ks][0]), "=r"(a[ks][1]), "=r"(a[ks][2]), "=r"(a[ks][3])
                     : "r"(addr));
    }

    const float invT = 1.f / TEMP;
    float negs_lo = 0.f, negs_hi = 0.f;
#pragma unroll
    for (int nt = 0; nt < 8; nt++) {
        float c0 = 0.f, c1 = 0.f, c2 = 0.f, c3 = 0.f;
#pragma unroll
        for (int ks = 0; ks < 4; ks++) {
            int br = nt * 8 + (lane & 7);
            int bc = ks * 16 + ((lane >> 3) & 1) * 8;
            unsigned baddr = (unsigned)__cvta_generic_to_shared(&Bs[br * XS + bc]);
            unsigned b0, b1;
            asm volatile("ldmatrix.sync.aligned.m8n8.x2.shared.b16 {%0,%1}, [%2];"
                         : "=r"(b0), "=r"(b1) : "r"(baddr));
            asm volatile("mma.sync.aligned.m16n8k16.row.col.f32.f16.f16.f32 "
                         "{%0,%1,%2,%3}, {%4,%5,%6,%7}, {%8,%9}, {%0,%1,%2,%3};"
                         : "+f"(c0), "+f"(c1), "+f"(c2), "+f"(c3)
                         : "r"(a[ks][0]), "r"(a[ks][1]), "r"(a[ks][2]), "r"(a[ks][3]),
                           "r"(b0), "r"(b1));
        }
        float sl = __expf(c0 * invT) + __expf(c1 * invT);
        float sh = __expf(c2 * invT) + __expf(c3 * invT);
        sl += __shfl_xor_sync(0xffffffffu, sl, 1);
        sl += __shfl_xor_sync(0xffffffffu, sl, 2);
        sh += __shfl_xor_sync(0xffffffffu, sh, 1);
        sh += __shfl_xor_sync(0xffffffffu, sh, 2);
        negs_lo += sl;
        negs_hi += sh;
    }
    if ((lane & 3) == 0) {
        int r = lane >> 2;
        atomicAdd(&negbuf[i0 + w * 16 + r], negs_lo);
        atomicAdd(&negbuf[i0 + w * 16 + r + 8], negs_hi);
    }
}

// fused nce-final + output (single block of 256)
__global__ void k_final(float* __restrict__ out) {
    int tid = threadIdx.x;
    float cl = 0.f;
    for (int i = tid; i < 2 * BB; i += 256)
        cl += -logf(g_pos[i] / (g_neg[i] + 1e-8f) + 1e-8f);
    float cltot = blkSum256(cl);
    if (tid == 0) {
        float bpr = g_sums[0] / (float)BB;
        float kl  = KL_REG * (g_sums[1] / (float)NN);
        out[0] = bpr + kl;
        out[1] = SSL_REG * (cltot / (float)BB);
        out[2] = EMB_REG * g_sums[2];
        out[3] = INT_REG * g_sums[3];
    }
}

// ---------------- launch ------------------------------------------------------
extern "C" void kernel_launch(void* const* d_in, const int* in_sizes, int n_in,
                              void* d_out, int out_size) {
    const float* user_emb = (const float*)d_in[0];
    const float* item_emb = (const float*)d_in[1];
    const float* uintm    = (const float*)d_in[2];
    const float* iintm    = (const float*)d_in[3];
    const float* lw       = (const float*)d_in[4];
    const float* lb       = (const float*)d_in[5];
    const float* eps      = (const float*)d_in[6];
    const int*   hl       = (const int*)d_in[7];
    const int*   tl       = (const int*)d_in[8];
    const int*   users    = (const int*)d_in[9];
    const int*   pos      = (const int*)d_in[10];
    const int*   neg      = (const int*)d_in[11];
    int E = in_sizes[7];
    float* out = (float*)d_out;

    void *p_cur, *p_nxt;
    cudaGetSymbolAddress(&p_cur, g_curb);
    cudaGetSymbolAddress(&p_nxt, g_nxtb);

    k_clear<<<(NN + 255) / 256, 256>>>();
    k_deg<<<(E + 255) / 256, 256>>>(hl, E);
    k_scanA<<<NBLK_SCAN, 256>>>();
    k_scanB<<<1, 32>>>();
    k_scanC<<<NBLK_SCAN, 256>>>();
    k_scatter<<<(E + 255) / 256, 256>>>(hl, tl, E);
    k_init<<<(NN * (DD / 2) + 255) / 256, 256>>>(user_emb, item_emb);

    k_prop<<<(NN * 32 + 255) / 256, 256>>>((const unsigned*)p_cur, (unsigned*)p_nxt);
    k_prop<<<(NN * 32 + 255) / 256, 256>>>((const unsigned*)p_nxt, (unsigned*)p_cur);
    k_prop<<<(NN * 32 + 255) / 256, 256>>>((const unsigned*)p_cur, (unsigned*)p_nxt);

    k_kl<<<(NN + 3) / 4, 256>>>(lw, lb);
    k_bpr<<<(BB * 32 + 255) / 256, 256>>>(user_emb, item_emb, users, pos, neg);
    k_intreg<<<(2 * DD * NI + 255) / 256, 256>>>(uintm, iintm);
    k_sample<<<2 * BB / SPB, 128>>>(lw, lb, eps, uintm, iintm, users, pos);

    {
        dim3 grid(BB / 128, BB / 64, 2);
        k_nce_mma<<<grid, 256>>>();
    }
    k_final<<<1, 256>>>(out);
}